// round 16
// baseline (speedup 1.0000x reference)
#include <cuda_runtime.h>

// ---------------------------------------------------------------------------
// Problem constants (fixed shapes from reference setup_inputs)
// ---------------------------------------------------------------------------
#define BB   4       // batch
#define NQ   8192    // query points (N)
#define MR   2048    // reference points (M)
#define C1C  128     // points1 channels
#define C2C  256     // points2 channels
#define K0C  384     // C2 + C1 (gemm0 K)
#define H0C  256     // conv0 out channels (gemm1 K)
#define H1C  128     // conv1 out channels
#define BN_EPS 1e-5f
#define CLAMP_V 1e-10f

// ---------------------------------------------------------------------------
// Scratch (static device globals: allocation-free)
// ---------------------------------------------------------------------------
__device__ int    g_idx[BB * NQ * 3];
__device__ float  g_w[BB * NQ * 3];
__device__ float  g_interp[BB * C2C * NQ];   // (B,256,N)  ~33.5 MB
__device__ float  g_y0[BB * H0C * NQ];       // (B,256,N)  ~33.5 MB (conv0 pre-BN)
__device__ float  g_wt0[K0C * H0C];          // W0 transposed: [k][o]
__device__ float  g_wt1[H0C * H1C];          // W1 transposed: [k][o]
__device__ float2 g_bn0[H0C];                // (scale, shift) for BN0
__device__ float2 g_bn1[H1C];                // (scale, shift) for BN1

// ---------------------------------------------------------------------------
// Kernel 1: 3-NN + combined (distance x normal) weights
// grid (NQ/256, B), block 256
// ---------------------------------------------------------------------------
__global__ void knn_kernel(const float* __restrict__ xyz1,
                           const float* __restrict__ xyz2,
                           const float* __restrict__ norm1,
                           const float* __restrict__ norm2)
{
    __shared__ float4 sp[MR];   // (x, y, z, |p|^2)  32 KB

    const int b   = blockIdx.y;
    const int tid = threadIdx.x;

    const float* x2 = xyz2 + b * 3 * MR;
    for (int j = tid; j < MR; j += blockDim.x) {
        float px = x2[j], py = x2[MR + j], pz = x2[2 * MR + j];
        sp[j] = make_float4(px, py, pz, px * px + py * py + pz * pz);
    }
    __syncthreads();

    const int n = blockIdx.x * blockDim.x + tid;
    const float* x1 = xyz1 + b * 3 * NQ;
    const float qx = x1[n], qy = x1[NQ + n], qz = x1[2 * NQ + n];
    const float qq = qx * qx + qy * qy + qz * qz;

    float bd0 = 3.4e38f, bd1 = 3.4e38f, bd2 = 3.4e38f;
    int   bi0 = 0, bi1 = 0, bi2 = 0;

    for (int j = 0; j < MR; j++) {
        float4 p = sp[j];
        float t = qx * p.x;
        t = fmaf(qy, p.y, t);
        t = fmaf(qz, p.z, t);
        float d = fmaf(-2.0f, t, qq + p.w);   // |q|^2 + |p|^2 - 2 q.p
        if (d < bd2) {
            if (d < bd1) {
                bd2 = bd1; bi2 = bi1;
                if (d < bd0) { bd1 = bd0; bi1 = bi0; bd0 = d; bi0 = j; }
                else         { bd1 = d;   bi1 = j; }
            } else {
                bd2 = d; bi2 = j;
            }
        }
    }

    // distance weights
    float dist0 = sqrtf(fmaxf(bd0, 1e-20f));
    float dist1 = sqrtf(fmaxf(bd1, 1e-20f));
    float dist2 = sqrtf(fmaxf(bd2, 1e-20f));
    float r0 = 1.0f / fmaxf(dist0, CLAMP_V);
    float r1 = 1.0f / fmaxf(dist1, CLAMP_V);
    float r2 = 1.0f / fmaxf(dist2, CLAMP_V);
    float rs = r0 + r1 + r2;

    // normal-distance weights
    const float* n1 = norm1 + b * 3 * NQ;
    const float nx = n1[n], ny = n1[NQ + n], nz = n1[2 * NQ + n];
    const float* n2 = norm2 + b * 3 * MR;
    float rn[3];
    int   bi[3] = { bi0, bi1, bi2 };
    #pragma unroll
    for (int k = 0; k < 3; k++) {
        int i = bi[k];
        float dx = nx - n2[i];
        float dy = ny - n2[MR + i];
        float dz = nz - n2[2 * MR + i];
        float nd = sqrtf(dx * dx + dy * dy + dz * dz);
        rn[k] = 1.0f / fmaxf(nd, CLAMP_V);
    }
    float rns = rn[0] + rn[1] + rn[2];

    const float inv = 1.0f / (rs * rns);
    const int base = (b * NQ + n) * 3;
    g_idx[base + 0] = bi0;  g_w[base + 0] = r0 * rn[0] * inv;
    g_idx[base + 1] = bi1;  g_w[base + 1] = r1 * rn[1] * inv;
    g_idx[base + 2] = bi2;  g_w[base + 2] = r2 * rn[2] * inv;
}

// ---------------------------------------------------------------------------
// Kernel 2: transpose W0 / W1 for coalesced GEMM loads
// ---------------------------------------------------------------------------
__global__ void prep_kernel(const float* __restrict__ W0,
                            const float* __restrict__ W1)
{
    int t = blockIdx.x * blockDim.x + threadIdx.x;
    if (t < K0C * H0C) {
        int o = t / K0C, k = t % K0C;
        g_wt0[k * H0C + o] = W0[t];
    }
    if (t < H0C * H1C) {
        int o = t / H0C, k = t % H0C;
        g_wt1[k * H1C + o] = W1[t];
    }
}

// ---------------------------------------------------------------------------
// Kernel 3: three_interpolate -> g_interp (B,256,N)
// grid (NQ/128, B), block 256
// ---------------------------------------------------------------------------
__global__ void interp_kernel(const float* __restrict__ points2)
{
    __shared__ int   si[128 * 3];
    __shared__ float sw[128 * 3];

    const int b   = blockIdx.y;
    const int n0  = blockIdx.x * 128;
    const int tid = threadIdx.x;

    const int gbase = (b * NQ + n0) * 3;
    for (int t = tid; t < 128 * 3; t += 256) {
        si[t] = g_idx[gbase + t];
        sw[t] = g_w[gbase + t];
    }
    __syncthreads();

    const int nl = tid & 127;
    const int i0 = si[nl * 3 + 0], i1 = si[nl * 3 + 1], i2 = si[nl * 3 + 2];
    const float w0 = sw[nl * 3 + 0], w1 = sw[nl * 3 + 1], w2 = sw[nl * 3 + 2];

    const float* p2  = points2 + (size_t)b * C2C * MR;
    float* outp      = g_interp + (size_t)b * C2C * NQ + n0 + nl;

    for (int c = (tid >> 7); c < C2C; c += 2) {
        const float* row = p2 + c * MR;
        float v = w0 * row[i0];
        v = fmaf(w1, row[i1], v);
        v = fmaf(w2, row[i2], v);
        outp[(size_t)c * NQ] = v;
    }
}

// ---------------------------------------------------------------------------
// GEMM0: y0[b,o,n] = sum_k W0[o,k] * X[b,k,n] + b0[o]
//   X rows 0..255 = g_interp, rows 256..383 = points1
// 64x64 tile, K-chunk 16, 4x4 micro-tile, 256 threads
// grid (NQ/64, H0/64, B)
// ---------------------------------------------------------------------------
__global__ void __launch_bounds__(256)
gemm0_kernel(const float* __restrict__ b0, const float* __restrict__ points1)
{
    __shared__ float Ws[16][64];
    __shared__ float Xs[16][64];

    const int b   = blockIdx.z;
    const int o0  = blockIdx.y * 64;
    const int n0  = blockIdx.x * 64;
    const int tid = threadIdx.x;

    const int lkk = tid >> 4;          // 0..15  (k within chunk)
    const int lc4 = (tid & 15) * 4;    // 0,4,...,60
    const int ty4 = (tid >> 4) * 4;    // output-channel sub-offset
    const int tx4 = (tid & 15) * 4;    // output-n sub-offset

    const float* interp_b = g_interp + (size_t)b * C2C * NQ;
    const float* p1_b     = points1  + (size_t)b * C1C * NQ;

    float acc[4][4] = {};

    for (int kc = 0; kc < K0C; kc += 16) {
        const int k = kc + lkk;
        *(float4*)&Ws[lkk][lc4] = *(const float4*)&g_wt0[k * H0C + o0 + lc4];
        const float* src = (k < C2C) ? (interp_b + (size_t)k * NQ)
                                     : (p1_b + (size_t)(k - C2C) * NQ);
        *(float4*)&Xs[lkk][lc4] = *(const float4*)&src[n0 + lc4];
        __syncthreads();

        #pragma unroll
        for (int kk = 0; kk < 16; kk++) {
            float4 a = *(float4*)&Ws[kk][ty4];
            float4 x = *(float4*)&Xs[kk][tx4];
            acc[0][0] = fmaf(a.x, x.x, acc[0][0]); acc[0][1] = fmaf(a.x, x.y, acc[0][1]);
            acc[0][2] = fmaf(a.x, x.z, acc[0][2]); acc[0][3] = fmaf(a.x, x.w, acc[0][3]);
            acc[1][0] = fmaf(a.y, x.x, acc[1][0]); acc[1][1] = fmaf(a.y, x.y, acc[1][1]);
            acc[1][2] = fmaf(a.y, x.z, acc[1][2]); acc[1][3] = fmaf(a.y, x.w, acc[1][3]);
            acc[2][0] = fmaf(a.z, x.x, acc[2][0]); acc[2][1] = fmaf(a.z, x.y, acc[2][1]);
            acc[2][2] = fmaf(a.z, x.z, acc[2][2]); acc[2][3] = fmaf(a.z, x.w, acc[2][3]);
            acc[3][0] = fmaf(a.w, x.x, acc[3][0]); acc[3][1] = fmaf(a.w, x.y, acc[3][1]);
            acc[3][2] = fmaf(a.w, x.z, acc[3][2]); acc[3][3] = fmaf(a.w, x.w, acc[3][3]);
        }
        __syncthreads();
    }

    #pragma unroll
    for (int i = 0; i < 4; i++) {
        const int o = o0 + ty4 + i;
        const float bias = b0[o];
        float4 r = make_float4(acc[i][0] + bias, acc[i][1] + bias,
                               acc[i][2] + bias, acc[i][3] + bias);
        *(float4*)&g_y0[((size_t)b * H0C + o) * NQ + n0 + tx4] = r;
    }
}

// ---------------------------------------------------------------------------
// BatchNorm stats: one block per channel -> (scale, shift)
// ---------------------------------------------------------------------------
__device__ __forceinline__ void stats_body(const float* __restrict__ y, int C,
                                           const float* __restrict__ g,
                                           const float* __restrict__ be,
                                           float2* __restrict__ bn)
{
    const int c   = blockIdx.x;
    const int tid = threadIdx.x;
    float s = 0.f, s2 = 0.f;
    for (int b = 0; b < BB; b++) {
        const float* row = y + ((size_t)b * C + c) * NQ;
        for (int n = tid; n < NQ; n += 256) {
            float v = row[n];
            s += v; s2 = fmaf(v, v, s2);
        }
    }
    #pragma unroll
    for (int o = 16; o; o >>= 1) {
        s  += __shfl_down_sync(0xFFFFFFFFu, s, o);
        s2 += __shfl_down_sync(0xFFFFFFFFu, s2, o);
    }
    __shared__ float rs[8], rs2[8];
    const int w = tid >> 5, l = tid & 31;
    if (l == 0) { rs[w] = s; rs2[w] = s2; }
    __syncthreads();
    if (tid == 0) {
        s = 0.f; s2 = 0.f;
        #pragma unroll
        for (int i = 0; i < 8; i++) { s += rs[i]; s2 += rs2[i]; }
        const float inv  = 1.0f / (float)(BB * NQ);
        const float mean = s * inv;
        const float var  = fmaxf(s2 * inv - mean * mean, 0.f);
        const float rstd = rsqrtf(var + BN_EPS);
        const float scale = rstd * g[c];
        bn[c] = make_float2(scale, be[c] - mean * scale);
    }
}

__global__ void stats0_kernel(const float* __restrict__ g, const float* __restrict__ be)
{ stats_body(g_y0, H0C, g, be, g_bn0); }

__global__ void stats1_kernel(const float* __restrict__ y1,
                              const float* __restrict__ g, const float* __restrict__ be)
{ stats_body(y1, H1C, g, be, g_bn1); }

// ---------------------------------------------------------------------------
// GEMM1: out[b,o,n] = sum_k W1[o,k] * relu(BN0(y0[b,k,n])) + b1[o]
// BN0+ReLU applied during the X-tile load. Writes RAW conv output to d_out.
// grid (NQ/64, H1/64, B)
// ---------------------------------------------------------------------------
__global__ void __launch_bounds__(256)
gemm1_kernel(const float* __restrict__ b1, float* __restrict__ out)
{
    __shared__ float Ws[16][64];
    __shared__ float Xs[16][64];

    const int b   = blockIdx.z;
    const int o0  = blockIdx.y * 64;
    const int n0  = blockIdx.x * 64;
    const int tid = threadIdx.x;

    const int lkk = tid >> 4;
    const int lc4 = (tid & 15) * 4;
    const int ty4 = (tid >> 4) * 4;
    const int tx4 = (tid & 15) * 4;

    float acc[4][4] = {};

    for (int kc = 0; kc < H0C; kc += 16) {
        const int k = kc + lkk;
        *(float4*)&Ws[lkk][lc4] = *(const float4*)&g_wt1[k * H1C + o0 + lc4];
        float4 raw = *(const float4*)&g_y0[((size_t)b * H0C + k) * NQ + n0 + lc4];
        float2 bn = g_bn0[k];
        Xs[lkk][lc4 + 0] = fmaxf(fmaf(raw.x, bn.x, bn.y), 0.f);
        Xs[lkk][lc4 + 1] = fmaxf(fmaf(raw.y, bn.x, bn.y), 0.f);
        Xs[lkk][lc4 + 2] = fmaxf(fmaf(raw.z, bn.x, bn.y), 0.f);
        Xs[lkk][lc4 + 3] = fmaxf(fmaf(raw.w, bn.x, bn.y), 0.f);
        __syncthreads();

        #pragma unroll
        for (int kk = 0; kk < 16; kk++) {
            float4 a = *(float4*)&Ws[kk][ty4];
            float4 x = *(float4*)&Xs[kk][tx4];
            acc[0][0] = fmaf(a.x, x.x, acc[0][0]); acc[0][1] = fmaf(a.x, x.y, acc[0][1]);
            acc[0][2] = fmaf(a.x, x.z, acc[0][2]); acc[0][3] = fmaf(a.x, x.w, acc[0][3]);
            acc[1][0] = fmaf(a.y, x.x, acc[1][0]); acc[1][1] = fmaf(a.y, x.y, acc[1][1]);
            acc[1][2] = fmaf(a.y, x.z, acc[1][2]); acc[1][3] = fmaf(a.y, x.w, acc[1][3]);
            acc[2][0] = fmaf(a.z, x.x, acc[2][0]); acc[2][1] = fmaf(a.z, x.y, acc[2][1]);
            acc[2][2] = fmaf(a.z, x.z, acc[2][2]); acc[2][3] = fmaf(a.z, x.w, acc[2][3]);
            acc[3][0] = fmaf(a.w, x.x, acc[3][0]); acc[3][1] = fmaf(a.w, x.y, acc[3][1]);
            acc[3][2] = fmaf(a.w, x.z, acc[3][2]); acc[3][3] = fmaf(a.w, x.w, acc[3][3]);
        }
        __syncthreads();
    }

    #pragma unroll
    for (int i = 0; i < 4; i++) {
        const int o = o0 + ty4 + i;
        const float bias = b1[o];
        float4 r = make_float4(acc[i][0] + bias, acc[i][1] + bias,
                               acc[i][2] + bias, acc[i][3] + bias);
        *(float4*)&out[((size_t)b * H1C + o) * NQ + n0 + tx4] = r;
    }
}

// ---------------------------------------------------------------------------
// Final: in-place BN1 + ReLU on d_out
// ---------------------------------------------------------------------------
__global__ void bn_final_kernel(float* __restrict__ out)
{
    const int t = blockIdx.x * blockDim.x + threadIdx.x;   // < B*H1*NQ = 4194304
    const int c = (t / NQ) & (H1C - 1);
    float2 bn = g_bn1[c];
    out[t] = fmaxf(fmaf(out[t], bn.x, bn.y), 0.f);
}

// ---------------------------------------------------------------------------
// Launch
// ---------------------------------------------------------------------------
extern "C" void kernel_launch(void* const* d_in, const int* in_sizes, int n_in,
                              void* d_out, int out_size)
{
    const float* xyz1    = (const float*)d_in[0];
    const float* xyz2    = (const float*)d_in[1];
    const float* norm1   = (const float*)d_in[2];
    const float* norm2   = (const float*)d_in[3];
    const float* points1 = (const float*)d_in[4];
    const float* points2 = (const float*)d_in[5];
    const float* W0      = (const float*)d_in[6];
    const float* b0      = (const float*)d_in[7];
    const float* g0      = (const float*)d_in[8];
    const float* be0     = (const float*)d_in[9];
    const float* W1      = (const float*)d_in[10];
    const float* b1      = (const float*)d_in[11];
    const float* g1      = (const float*)d_in[12];
    const float* be1     = (const float*)d_in[13];
    float* out           = (float*)d_out;

    knn_kernel<<<dim3(NQ / 256, BB), 256>>>(xyz1, xyz2, norm1, norm2);
    prep_kernel<<<(K0C * H0C + 255) / 256, 256>>>(W0, W1);
    interp_kernel<<<dim3(NQ / 128, BB), 256>>>(points2);
    gemm0_kernel<<<dim3(NQ / 64, H0C / 64, BB), 256>>>(b0, points1);
    stats0_kernel<<<H0C, 256>>>(g0, be0);
    gemm1_kernel<<<dim3(NQ / 64, H1C / 64, BB), 256>>>(b1, out);
    stats1_kernel<<<H1C, 256>>>(out, g1, be1);
    bn_final_kernel<<<(BB * H1C * NQ) / 256, 256>>>(out);
}

// round 17
// speedup vs baseline: 1.0387x; 1.0387x over previous
#include <cuda_runtime.h>

// ---------------------------------------------------------------------------
// Problem constants (fixed shapes from reference setup_inputs)
// ---------------------------------------------------------------------------
#define BB   4       // batch
#define NQ   8192    // query points (N)
#define MR   2048    // reference points (M)
#define C1C  128     // points1 channels
#define C2C  256     // points2 channels
#define K0C  384     // C2 + C1 (gemm0 K)
#define H0C  256     // conv0 out channels (gemm1 K)
#define H1C  128     // conv1 out channels
#define BN_EPS 1e-5f
#define CLAMP_V 1e-10f

// ---------------------------------------------------------------------------
// Scratch (static device globals: allocation-free)
// ---------------------------------------------------------------------------
__device__ int    g_idx[BB * NQ * 3];
__device__ float  g_w[BB * NQ * 3];
__device__ float  g_interp[BB * C2C * NQ];   // (B,256,N)  ~33.5 MB
__device__ float  g_y0[BB * H0C * NQ];       // (B,256,N)  ~33.5 MB (conv0 pre-BN)
__device__ float  g_wt0[K0C * H0C];          // W0 transposed: [k][o]
__device__ float  g_wt1[H0C * H1C];          // W1 transposed: [k][o]
__device__ float2 g_bn0[H0C];                // (scale, shift) for BN0
__device__ float2 g_bn1[H1C];                // (scale, shift) for BN1

// ---------------------------------------------------------------------------
// Kernel 1: 3-NN + combined (distance x normal) weights
// ---------------------------------------------------------------------------
__global__ void knn_kernel(const float* __restrict__ xyz1,
                           const float* __restrict__ xyz2,
                           const float* __restrict__ norm1,
                           const float* __restrict__ norm2)
{
    __shared__ float4 sp[MR];   // (x, y, z, |p|^2)  32 KB

    const int b   = blockIdx.y;
    const int tid = threadIdx.x;

    const float* x2 = xyz2 + b * 3 * MR;
    for (int j = tid; j < MR; j += blockDim.x) {
        float px = x2[j], py = x2[MR + j], pz = x2[2 * MR + j];
        sp[j] = make_float4(px, py, pz, px * px + py * py + pz * pz);
    }
    __syncthreads();

    const int n = blockIdx.x * blockDim.x + tid;
    const float* x1 = xyz1 + b * 3 * NQ;
    const float qx = x1[n], qy = x1[NQ + n], qz = x1[2 * NQ + n];
    const float qq = qx * qx + qy * qy + qz * qz;

    float bd0 = 3.4e38f, bd1 = 3.4e38f, bd2 = 3.4e38f;
    int   bi0 = 0, bi1 = 0, bi2 = 0;

    for (int j = 0; j < MR; j++) {
        float4 p = sp[j];
        float t = qx * p.x;
        t = fmaf(qy, p.y, t);
        t = fmaf(qz, p.z, t);
        float d = fmaf(-2.0f, t, qq + p.w);
        if (d < bd2) {
            if (d < bd1) {
                bd2 = bd1; bi2 = bi1;
                if (d < bd0) { bd1 = bd0; bi1 = bi0; bd0 = d; bi0 = j; }
                else         { bd1 = d;   bi1 = j; }
            } else {
                bd2 = d; bi2 = j;
            }
        }
    }

    float dist0 = sqrtf(fmaxf(bd0, 1e-20f));
    float dist1 = sqrtf(fmaxf(bd1, 1e-20f));
    float dist2 = sqrtf(fmaxf(bd2, 1e-20f));
    float r0 = 1.0f / fmaxf(dist0, CLAMP_V);
    float r1 = 1.0f / fmaxf(dist1, CLAMP_V);
    float r2 = 1.0f / fmaxf(dist2, CLAMP_V);
    float rs = r0 + r1 + r2;

    const float* n1 = norm1 + b * 3 * NQ;
    const float nx = n1[n], ny = n1[NQ + n], nz = n1[2 * NQ + n];
    const float* n2 = norm2 + b * 3 * MR;
    float rn[3];
    int   bi[3] = { bi0, bi1, bi2 };
    #pragma unroll
    for (int k = 0; k < 3; k++) {
        int i = bi[k];
        float dx = nx - n2[i];
        float dy = ny - n2[MR + i];
        float dz = nz - n2[2 * MR + i];
        float nd = sqrtf(dx * dx + dy * dy + dz * dz);
        rn[k] = 1.0f / fmaxf(nd, CLAMP_V);
    }
    float rns = rn[0] + rn[1] + rn[2];

    const float inv = 1.0f / (rs * rns);
    const int base = (b * NQ + n) * 3;
    g_idx[base + 0] = bi0;  g_w[base + 0] = r0 * rn[0] * inv;
    g_idx[base + 1] = bi1;  g_w[base + 1] = r1 * rn[1] * inv;
    g_idx[base + 2] = bi2;  g_w[base + 2] = r2 * rn[2] * inv;
}

// ---------------------------------------------------------------------------
// Kernel 2: transpose W0 / W1
// ---------------------------------------------------------------------------
__global__ void prep_kernel(const float* __restrict__ W0,
                            const float* __restrict__ W1)
{
    int t = blockIdx.x * blockDim.x + threadIdx.x;
    if (t < K0C * H0C) {
        int o = t / K0C, k = t % K0C;
        g_wt0[k * H0C + o] = W0[t];
    }
    if (t < H0C * H1C) {
        int o = t / H0C, k = t % H0C;
        g_wt1[k * H1C + o] = W1[t];
    }
}

// ---------------------------------------------------------------------------
// Kernel 3: three_interpolate -> g_interp (B,256,N)
// ---------------------------------------------------------------------------
__global__ void interp_kernel(const float* __restrict__ points2)
{
    __shared__ int   si[128 * 3];
    __shared__ float sw[128 * 3];

    const int b   = blockIdx.y;
    const int n0  = blockIdx.x * 128;
    const int tid = threadIdx.x;

    const int gbase = (b * NQ + n0) * 3;
    for (int t = tid; t < 128 * 3; t += 256) {
        si[t] = g_idx[gbase + t];
        sw[t] = g_w[gbase + t];
    }
    __syncthreads();

    const int nl = tid & 127;
    const int i0 = si[nl * 3 + 0], i1 = si[nl * 3 + 1], i2 = si[nl * 3 + 2];
    const float w0 = sw[nl * 3 + 0], w1 = sw[nl * 3 + 1], w2 = sw[nl * 3 + 2];

    const float* p2  = points2 + (size_t)b * C2C * MR;
    float* outp      = g_interp + (size_t)b * C2C * NQ + n0 + nl;

    for (int c = (tid >> 7); c < C2C; c += 2) {
        const float* row = p2 + c * MR;
        float v = w0 * row[i0];
        v = fmaf(w1, row[i1], v);
        v = fmaf(w2, row[i2], v);
        outp[(size_t)c * NQ] = v;
    }
}

// ---------------------------------------------------------------------------
// GEMM0: y0[b,o,n] = sum_k W0[o,k] * X[b,k,n] + b0[o]
//   128x128 block tile, BK=8, 8x8 micro-tile (2x4 + 2x4 split), 256 threads
//   grid (NQ/128, H0/128, B)
// ---------------------------------------------------------------------------
__global__ void __launch_bounds__(256, 2)
gemm0_kernel(const float* __restrict__ b0, const float* __restrict__ points1)
{
    __shared__ float Ws[8][128];
    __shared__ float Xs[8][128];

    const int b   = blockIdx.z;
    const int o0  = blockIdx.y * 128;
    const int n0  = blockIdx.x * 128;
    const int tid = threadIdx.x;

    const int lk  = tid >> 5;          // 0..7   load row (k within chunk)
    const int lc4 = (tid & 31) * 4;    // 0..124 load col

    const int ty4 = (tid >> 4) * 4;    // 0..60  o sub-offset
    const int tx4 = (tid & 15) * 4;    // 0..60  n sub-offset

    const float* interp_b = g_interp + (size_t)b * C2C * NQ;
    const float* p1_b     = points1  + (size_t)b * C1C * NQ;

    float acc[8][8];
    #pragma unroll
    for (int i = 0; i < 8; i++)
        #pragma unroll
        for (int j = 0; j < 8; j++) acc[i][j] = 0.f;

    for (int kc = 0; kc < K0C; kc += 8) {
        const int k = kc + lk;
        *(float4*)&Ws[lk][lc4] = *(const float4*)&g_wt0[k * H0C + o0 + lc4];
        const float* src = (k < C2C) ? (interp_b + (size_t)k * NQ)
                                     : (p1_b + (size_t)(k - C2C) * NQ);
        *(float4*)&Xs[lk][lc4] = *(const float4*)&src[n0 + lc4];
        __syncthreads();

        #pragma unroll
        for (int kk = 0; kk < 8; kk++) {
            float a[8], x[8];
            *(float4*)&a[0] = *(float4*)&Ws[kk][ty4];
            *(float4*)&a[4] = *(float4*)&Ws[kk][64 + ty4];
            *(float4*)&x[0] = *(float4*)&Xs[kk][tx4];
            *(float4*)&x[4] = *(float4*)&Xs[kk][64 + tx4];
            #pragma unroll
            for (int i = 0; i < 8; i++)
                #pragma unroll
                for (int j = 0; j < 8; j++)
                    acc[i][j] = fmaf(a[i], x[j], acc[i][j]);
        }
        __syncthreads();
    }

    #pragma unroll
    for (int ih = 0; ih < 2; ih++) {
        #pragma unroll
        for (int i = 0; i < 4; i++) {
            const int o = o0 + ih * 64 + ty4 + i;
            const float bias = b0[o];
            float* row = &g_y0[((size_t)b * H0C + o) * NQ + n0];
            const float* ai = acc[ih * 4 + i];
            *(float4*)&row[tx4]      = make_float4(ai[0] + bias, ai[1] + bias,
                                                   ai[2] + bias, ai[3] + bias);
            *(float4*)&row[64 + tx4] = make_float4(ai[4] + bias, ai[5] + bias,
                                                   ai[6] + bias, ai[7] + bias);
        }
    }
}

// ---------------------------------------------------------------------------
// BatchNorm stats: one block per channel -> (scale, shift)
// ---------------------------------------------------------------------------
__device__ __forceinline__ void stats_body(const float* __restrict__ y, int C,
                                           const float* __restrict__ g,
                                           const float* __restrict__ be,
                                           float2* __restrict__ bn)
{
    const int c   = blockIdx.x;
    const int tid = threadIdx.x;
    float s = 0.f, s2 = 0.f;
    for (int b = 0; b < BB; b++) {
        const float* row = y + ((size_t)b * C + c) * NQ;
        for (int n = tid; n < NQ; n += 256) {
            float v = row[n];
            s += v; s2 = fmaf(v, v, s2);
        }
    }
    #pragma unroll
    for (int o = 16; o; o >>= 1) {
        s  += __shfl_down_sync(0xFFFFFFFFu, s, o);
        s2 += __shfl_down_sync(0xFFFFFFFFu, s2, o);
    }
    __shared__ float rs[8], rs2[8];
    const int w = tid >> 5, l = tid & 31;
    if (l == 0) { rs[w] = s; rs2[w] = s2; }
    __syncthreads();
    if (tid == 0) {
        s = 0.f; s2 = 0.f;
        #pragma unroll
        for (int i = 0; i < 8; i++) { s += rs[i]; s2 += rs2[i]; }
        const float inv  = 1.0f / (float)(BB * NQ);
        const float mean = s * inv;
        const float var  = fmaxf(s2 * inv - mean * mean, 0.f);
        const float rstd = rsqrtf(var + BN_EPS);
        const float scale = rstd * g[c];
        bn[c] = make_float2(scale, be[c] - mean * scale);
    }
}

__global__ void stats0_kernel(const float* __restrict__ g, const float* __restrict__ be)
{ stats_body(g_y0, H0C, g, be, g_bn0); }

__global__ void stats1_kernel(const float* __restrict__ y1,
                              const float* __restrict__ g, const float* __restrict__ be)
{ stats_body(y1, H1C, g, be, g_bn1); }

// ---------------------------------------------------------------------------
// GEMM1: out[b,o,n] = sum_k W1[o,k] * relu(BN0(y0[b,k,n])) + b1[o]
//   128x128 block tile (o-tile = full H1C), BK=8, 8x8 micro-tile, 256 threads
//   grid (NQ/128, 1, B)
// ---------------------------------------------------------------------------
__global__ void __launch_bounds__(256, 2)
gemm1_kernel(const float* __restrict__ b1, float* __restrict__ out)
{
    __shared__ float Ws[8][128];
    __shared__ float Xs[8][128];

    const int b   = blockIdx.z;
    const int o0  = blockIdx.y * 128;
    const int n0  = blockIdx.x * 128;
    const int tid = threadIdx.x;

    const int lk  = tid >> 5;
    const int lc4 = (tid & 31) * 4;
    const int ty4 = (tid >> 4) * 4;
    const int tx4 = (tid & 15) * 4;

    float acc[8][8];
    #pragma unroll
    for (int i = 0; i < 8; i++)
        #pragma unroll
        for (int j = 0; j < 8; j++) acc[i][j] = 0.f;

    for (int kc = 0; kc < H0C; kc += 8) {
        const int k = kc + lk;
        *(float4*)&Ws[lk][lc4] = *(const float4*)&g_wt1[k * H1C + o0 + lc4];
        float4 raw = *(const float4*)&g_y0[((size_t)b * H0C + k) * NQ + n0 + lc4];
        float2 bn = g_bn0[k];
        Xs[lk][lc4 + 0] = fmaxf(fmaf(raw.x, bn.x, bn.y), 0.f);
        Xs[lk][lc4 + 1] = fmaxf(fmaf(raw.y, bn.x, bn.y), 0.f);
        Xs[lk][lc4 + 2] = fmaxf(fmaf(raw.z, bn.x, bn.y), 0.f);
        Xs[lk][lc4 + 3] = fmaxf(fmaf(raw.w, bn.x, bn.y), 0.f);
        __syncthreads();

        #pragma unroll
        for (int kk = 0; kk < 8; kk++) {
            float a[8], x[8];
            *(float4*)&a[0] = *(float4*)&Ws[kk][ty4];
            *(float4*)&a[4] = *(float4*)&Ws[kk][64 + ty4];
            *(float4*)&x[0] = *(float4*)&Xs[kk][tx4];
            *(float4*)&x[4] = *(float4*)&Xs[kk][64 + tx4];
            #pragma unroll
            for (int i = 0; i < 8; i++)
                #pragma unroll
                for (int j = 0; j < 8; j++)
                    acc[i][j] = fmaf(a[i], x[j], acc[i][j]);
        }
        __syncthreads();
    }

    #pragma unroll
    for (int ih = 0; ih < 2; ih++) {
        #pragma unroll
        for (int i = 0; i < 4; i++) {
            const int o = o0 + ih * 64 + ty4 + i;
            const float bias = b1[o];
            float* row = &out[((size_t)b * H1C + o) * NQ + n0];
            const float* ai = acc[ih * 4 + i];
            *(float4*)&row[tx4]      = make_float4(ai[0] + bias, ai[1] + bias,
                                                   ai[2] + bias, ai[3] + bias);
            *(float4*)&row[64 + tx4] = make_float4(ai[4] + bias, ai[5] + bias,
                                                   ai[6] + bias, ai[7] + bias);
        }
    }
}

// ---------------------------------------------------------------------------
// Final: in-place BN1 + ReLU on d_out
// ---------------------------------------------------------------------------
__global__ void bn_final_kernel(float* __restrict__ out)
{
    const int t = blockIdx.x * blockDim.x + threadIdx.x;
    const int c = (t / NQ) & (H1C - 1);
    float2 bn = g_bn1[c];
    out[t] = fmaxf(fmaf(out[t], bn.x, bn.y), 0.f);
}

// ---------------------------------------------------------------------------
// Launch
// ---------------------------------------------------------------------------
extern "C" void kernel_launch(void* const* d_in, const int* in_sizes, int n_in,
                              void* d_out, int out_size)
{
    const float* xyz1    = (const float*)d_in[0];
    const float* xyz2    = (const float*)d_in[1];
    const float* norm1   = (const float*)d_in[2];
    const float* norm2   = (const float*)d_in[3];
    const float* points1 = (const float*)d_in[4];
    const float* points2 = (const float*)d_in[5];
    const float* W0      = (const float*)d_in[6];
    const float* b0      = (const float*)d_in[7];
    const float* g0      = (const float*)d_in[8];
    const float* be0     = (const float*)d_in[9];
    const float* W1      = (const float*)d_in[10];
    const float* b1      = (const float*)d_in[11];
    const float* g1      = (const float*)d_in[12];
    const float* be1     = (const float*)d_in[13];
    float* out           = (float*)d_out;

    knn_kernel<<<dim3(NQ / 256, BB), 256>>>(xyz1, xyz2, norm1, norm2);
    prep_kernel<<<(K0C * H0C + 255) / 256, 256>>>(W0, W1);
    interp_kernel<<<dim3(NQ / 128, BB), 256>>>(points2);
    gemm0_kernel<<<dim3(NQ / 128, H0C / 128, BB), 256>>>(b0, points1);
    stats0_kernel<<<H0C, 256>>>(g0, be0);
    gemm1_kernel<<<dim3(NQ / 128, H1C / 128, BB), 256>>>(b1, out);
    stats1_kernel<<<H1C, 256>>>(out, g1, be1);
    bn_final_kernel<<<(BB * H1C * NQ) / 256, 256>>>(out);
}